// round 2
// baseline (speedup 1.0000x reference)
#include <cuda_runtime.h>
#include <cuda_bf16.h>
#include <math.h>
#include <limits.h>

// Problem constants (fixed shapes per reference setup_inputs)
#define NN 50000
#define FF 128
#define H1 8
#define C1 8
#define HC1 64   // H1*C1

// ---------------- scratch (device globals; 16B aligned for float4/red.v4) ----
__device__ __align__(16) float g_h1[NN * HC1];     // layer1 features [N,64]
__device__ float g_as1[NN * H1];
__device__ float g_ad1[NN * H1];
__device__ int   g_m1[NN * H1];                    // segment max (ordered int)
__device__ float g_s1[NN * H1];                    // segment sum of exp
__device__ __align__(16) float g_acc1[NN * HC1];   // unnormalized accumulation
__device__ __align__(16) float g_x2[NN * HC1];     // ELU(layer1 out)
__device__ __align__(16) float g_h2[NN * FF];      // layer2 features [N,128]
__device__ float g_as2[NN];
__device__ float g_ad2[NN];
__device__ int   g_m2[NN];
__device__ float g_s2[NN];
__device__ int   g_is64;                           // edge_index dtype flag

// ---------------- helpers ----------------------------------------------------
__device__ __forceinline__ int f2o(float f) {
    int i = __float_as_int(f);
    return i >= 0 ? i : i ^ 0x7FFFFFFF;
}
__device__ __forceinline__ float o2f(int i) {
    return __int_as_float(i >= 0 ? i : i ^ 0x7FFFFFFF);
}
__device__ __forceinline__ float leaky(float x) {
    return x > 0.0f ? x : 0.2f * x;
}
__device__ __forceinline__ void red_add_v4(float* p, float a, float b, float c, float d) {
    asm volatile("red.global.add.v4.f32 [%0], {%1,%2,%3,%4};"
                 :: "l"(p), "f"(a), "f"(b), "f"(c), "f"(d) : "memory");
}
// Load edge endpoints, robust to int64-vs-int32 edge_index storage.
__device__ __forceinline__ void load_edge(const void* ei, int E, int e,
                                          int& src, int& dst) {
    if (g_is64) {
        const long long* p = (const long long*)ei;
        src = (int)p[e]; dst = (int)p[E + e];
    } else {
        const int* p = (const int*)ei;
        src = p[e]; dst = p[E + e];
    }
}

// ---------------- dtype probe -------------------------------------------------
// int64 little-endian values < 50000 -> odd 32-bit words are 0.
// int32 array -> odd words are random node ids (all-zero prob ~ (1/5e4)^8).
__global__ void k_detect(const int* __restrict__ ei32) {
    int is64 = 1;
#pragma unroll
    for (int i = 0; i < 8; i++)
        if (ei32[2 * i + 1] != 0) is64 = 0;
    g_is64 = is64;
}

// ---------------- init: zero/seed all accumulators ---------------------------
__global__ void k_init(float* __restrict__ out, int N) {
    int total = N * FF;
    for (int i = blockIdx.x * blockDim.x + threadIdx.x; i < total;
         i += gridDim.x * blockDim.x) {
        out[i] = 0.0f;
        if (i < N * HC1) g_acc1[i] = 0.0f;
        if (i < N * H1) { g_m1[i] = INT_MIN; g_s1[i] = 0.0f; }
        if (i < N)      { g_m2[i] = INT_MIN; g_s2[i] = 0.0f; }
    }
}

// ---------------- layer1 GEMM + per-node attention logits --------------------
// one block per node, 64 threads (one per output channel of h1)
__global__ void k_gemm1(const float* __restrict__ x, const float* __restrict__ W1,
                        const float* __restrict__ att_s, const float* __restrict__ att_d) {
    int n = blockIdx.x;
    int t = threadIdx.x;  // 0..63
    __shared__ float xs[FF];
    __shared__ float hs[HC1];
    xs[t]      = x[n * FF + t];
    xs[t + 64] = x[n * FF + 64 + t];
    __syncthreads();
    float acc = 0.0f;
#pragma unroll
    for (int k = 0; k < FF; k++) acc = fmaf(xs[k], W1[k * HC1 + t], acc);
    g_h1[n * HC1 + t] = acc;
    hs[t] = acc;
    __syncthreads();
    if (t < H1) {
        float a = 0.0f;
#pragma unroll
        for (int c = 0; c < C1; c++) a = fmaf(hs[t * C1 + c], att_s[t * C1 + c], a);
        g_as1[n * H1 + t] = a;
    } else if (t < 2 * H1) {
        int h = t - H1;
        float a = 0.0f;
#pragma unroll
        for (int c = 0; c < C1; c++) a = fmaf(hs[h * C1 + c], att_d[h * C1 + c], a);
        g_ad1[n * H1 + h] = a;
    }
}

// ---------------- layer1 edge pass A: segment max ----------------------------
__global__ void k_max1(const void* __restrict__ ei, int E, int Etot) {
    int e = blockIdx.x * blockDim.x + threadIdx.x;
    if (e >= Etot) return;
    int src, dst;
    if (e < E) load_edge(ei, E, e, src, dst);
    else       src = dst = e - E;
#pragma unroll
    for (int h = 0; h < H1; h++) {
        float ee = leaky(g_as1[src * H1 + h] + g_ad1[dst * H1 + h]);
        atomicMax(&g_m1[dst * H1 + h], f2o(ee));
    }
}

// ---------------- layer1 edge pass B: exp + scatter-accumulate ---------------
// half-warp (16 lanes) per edge; lane l: head = l>>1, 4-channel chunk = (l&1)*4
__global__ void k_acc1(const void* __restrict__ ei, int E, int Etot) {
    int warp = (blockIdx.x * blockDim.x + threadIdx.x) >> 5;
    int lane = threadIdx.x & 31;
    int hw = lane >> 4;
    int l  = lane & 15;
    int e = warp * 2 + hw;
    if (e >= Etot) return;
    int src, dst;
    if (e < E) load_edge(ei, E, e, src, dst);
    else       src = dst = e - E;
    int head  = l >> 1;
    int chunk = (l & 1) * 4;
    float ee = leaky(g_as1[src * H1 + head] + g_ad1[dst * H1 + head]);
    float m  = o2f(g_m1[dst * H1 + head]);
    float ex = __expf(ee - m);
    if ((l & 1) == 0) atomicAdd(&g_s1[dst * H1 + head], ex);
    const float4 hv = *reinterpret_cast<const float4*>(&g_h1[src * HC1 + head * C1 + chunk]);
    red_add_v4(&g_acc1[dst * HC1 + head * C1 + chunk],
               ex * hv.x, ex * hv.y, ex * hv.z, ex * hv.w);
}

// ---------------- layer1 finalize: normalize + bias + ELU --------------------
__global__ void k_fin1(const float* __restrict__ b1, int N) {
    int total = N * HC1;
    for (int i = blockIdx.x * blockDim.x + threadIdx.x; i < total;
         i += gridDim.x * blockDim.x) {
        int n = i / HC1, j = i % HC1, h = j / C1;
        float s = g_s1[n * H1 + h];
        s = s > 0.0f ? s : 1.0f;
        float v = g_acc1[i] / s + b1[j];
        g_x2[i] = v > 0.0f ? v : expm1f(v);
    }
}

// ---------------- layer2 GEMM + attention logits -----------------------------
// one block per node, 128 threads (one per output channel)
__global__ void k_gemm2(const float* __restrict__ W2, const float* __restrict__ att_s,
                        const float* __restrict__ att_d) {
    int n = blockIdx.x;
    int t = threadIdx.x;  // 0..127
    __shared__ float xs[HC1];
    __shared__ float rs[FF];
    __shared__ float rd[FF];
    if (t < HC1) xs[t] = g_x2[n * HC1 + t];
    __syncthreads();
    float acc = 0.0f;
#pragma unroll
    for (int k = 0; k < HC1; k++) acc = fmaf(xs[k], W2[k * FF + t], acc);
    g_h2[n * FF + t] = acc;
    rs[t] = acc * att_s[t];
    rd[t] = acc * att_d[t];
    __syncthreads();
    for (int off = 64; off > 0; off >>= 1) {
        if (t < off) { rs[t] += rs[t + off]; rd[t] += rd[t + off]; }
        __syncthreads();
    }
    if (t == 0) { g_as2[n] = rs[0]; g_ad2[n] = rd[0]; }
}

// ---------------- layer2 edge pass A: segment max ----------------------------
__global__ void k_max2(const void* __restrict__ ei, int E, int Etot) {
    int e = blockIdx.x * blockDim.x + threadIdx.x;
    if (e >= Etot) return;
    int src, dst;
    if (e < E) load_edge(ei, E, e, src, dst);
    else       src = dst = e - E;
    float ee = leaky(g_as2[src] + g_ad2[dst]);
    atomicMax(&g_m2[dst], f2o(ee));
}

// ---------------- layer2 edge pass B: exp + scatter-accumulate ---------------
// one warp per edge; lane handles 4 channels (32*4 = 128)
__global__ void k_acc2(const void* __restrict__ ei, int E, int Etot,
                       float* __restrict__ out) {
    int warp = (blockIdx.x * blockDim.x + threadIdx.x) >> 5;
    int lane = threadIdx.x & 31;
    int e = warp;
    if (e >= Etot) return;
    int src, dst;
    if (e < E) load_edge(ei, E, e, src, dst);
    else       src = dst = e - E;
    float ee = leaky(g_as2[src] + g_ad2[dst]);
    float m  = o2f(g_m2[dst]);
    float ex = __expf(ee - m);
    if (lane == 0) atomicAdd(&g_s2[dst], ex);
    const float4 hv = *reinterpret_cast<const float4*>(&g_h2[src * FF + lane * 4]);
    red_add_v4(&out[dst * FF + lane * 4],
               ex * hv.x, ex * hv.y, ex * hv.z, ex * hv.w);
}

// ---------------- layer2 finalize: normalize + bias --------------------------
__global__ void k_fin2(float* __restrict__ out, const float* __restrict__ b2, int N) {
    int total = N * FF;
    for (int i = blockIdx.x * blockDim.x + threadIdx.x; i < total;
         i += gridDim.x * blockDim.x) {
        int n = i / FF, j = i % FF;
        float s = g_s2[n];
        s = s > 0.0f ? s : 1.0f;
        out[i] = out[i] / s + b2[j];
    }
}

// ---------------- launcher ----------------------------------------------------
extern "C" void kernel_launch(void* const* d_in, const int* in_sizes, int n_in,
                              void* d_out, int out_size) {
    const float* x   = (const float*)d_in[0];
    const void*  ei  = d_in[1];
    const float* W1  = (const float*)d_in[2];
    const float* as1 = (const float*)d_in[3];
    const float* ad1 = (const float*)d_in[4];
    const float* b1  = (const float*)d_in[5];
    const float* W2  = (const float*)d_in[6];
    const float* as2 = (const float*)d_in[7];
    const float* ad2 = (const float*)d_in[8];
    const float* b2  = (const float*)d_in[9];
    float*       out = (float*)d_out;

    int N    = in_sizes[0] / FF;     // 50000
    int E    = in_sizes[1] / 2;      // 800000
    int Etot = E + N;                // with self loops

    k_detect<<<1, 1>>>((const int*)ei);

    int initBlocks = (N * FF + 255) / 256;
    k_init<<<initBlocks, 256>>>(out, N);

    k_gemm1<<<N, 64>>>(x, W1, as1, ad1);

    k_max1<<<(Etot + 255) / 256, 256>>>(ei, E, Etot);

    // 2 edges per warp -> 16 edges per 256-thread block
    k_acc1<<<(Etot + 15) / 16, 256>>>(ei, E, Etot);

    k_fin1<<<(N * HC1 + 255) / 256, 256>>>(b1, N);

    k_gemm2<<<N, 128>>>(W2, as2, ad2);

    k_max2<<<(Etot + 255) / 256, 256>>>(ei, E, Etot);

    // 1 edge per warp -> 8 edges per 256-thread block
    k_acc2<<<(Etot + 7) / 8, 256>>>(ei, E, Etot, out);

    k_fin2<<<(N * FF + 255) / 256, 256>>>(out, b2, N);
}

// round 3
// speedup vs baseline: 1.9919x; 1.9919x over previous
#include <cuda_runtime.h>
#include <cuda_bf16.h>
#include <math.h>

// Fixed problem shape (per reference setup_inputs)
#define NN 50000
#define FF 128
#define H1 8
#define C1 8
#define HC1 64
#define EMAX 900000   // E (800000) + N (50000) self loops, padded

// ---------------- device scratch (no allocation allowed) ----------------
__device__ __align__(16) float g_h1[NN * HC1];   // layer1 features
__device__ __align__(16) float g_x2[NN * HC1];   // ELU(layer1 out)
__device__ __align__(16) float g_h2[NN * FF];    // layer2 features
__device__ float g_as1[NN * H1];
__device__ float g_ad1[NN * H1];
__device__ float g_as2[NN];
__device__ float g_ad2[NN];
__device__ int   g_rowptr[NN + 1];
__device__ int   g_cnt[NN];
__device__ int   g_col[EMAX];                    // src ids grouped by dst
__device__ int   g_is64;

// ---------------- helpers ----------------
__device__ __forceinline__ float leaky(float x) { return x > 0.0f ? x : 0.2f * x; }

__device__ __forceinline__ void load_edge(const void* ei, int E, int e,
                                          int& src, int& dst) {
    if (g_is64) {
        const long long* p = (const long long*)ei;
        src = (int)p[e]; dst = (int)p[E + e];
    } else {
        const int* p = (const int*)ei;
        src = p[e]; dst = p[E + e];
    }
}
__device__ __forceinline__ int load_dst(const void* ei, int E, int e) {
    if (g_is64) return (int)((const long long*)ei)[E + e];
    return ((const int*)ei)[E + e];
}

// ---------------- dtype probe: int64 values <50000 have zero odd words ----
__global__ void k_detect(const int* __restrict__ ei32) {
    int is64 = 1;
#pragma unroll
    for (int i = 0; i < 8; i++)
        if (ei32[2 * i + 1] != 0) is64 = 0;
    g_is64 = is64;
}

// ---------------- CSR build ----------------
__global__ void k_zero_cnt(int N) {
    int i = blockIdx.x * blockDim.x + threadIdx.x;
    if (i < N) g_cnt[i] = 0;
}

__global__ void k_hist(const void* __restrict__ ei, int E, int Etot) {
    int e = blockIdx.x * blockDim.x + threadIdx.x;
    if (e >= Etot) return;
    int dst = (e < E) ? load_dst(ei, E, e) : e - E;
    atomicAdd(&g_cnt[dst], 1);
}

// single-block exclusive scan of g_cnt -> g_rowptr
__global__ void k_scan(int N, int Etot) {
    __shared__ int ssum[1024];
    int t = threadIdx.x;
    int C = (N + 1023) >> 10;
    int lo = t * C;
    int hi = min(lo + C, N);
    int s = 0;
    for (int i = lo; i < hi; i++) s += g_cnt[i];
    ssum[t] = s;
    __syncthreads();
    for (int off = 1; off < 1024; off <<= 1) {
        int v = (t >= off) ? ssum[t - off] : 0;
        __syncthreads();
        ssum[t] += v;
        __syncthreads();
    }
    int run = (t > 0) ? ssum[t - 1] : 0;
    for (int i = lo; i < hi; i++) {
        int c = g_cnt[i];
        g_rowptr[i] = run;
        run += c;
    }
    if (t == 0) g_rowptr[N] = Etot;
}

__global__ void k_scatter(const void* __restrict__ ei, int E, int Etot) {
    int e = blockIdx.x * blockDim.x + threadIdx.x;
    if (e >= Etot) return;
    int src, dst;
    if (e < E) load_edge(ei, E, e, src, dst);
    else       src = dst = e - E;
    int pos = g_rowptr[dst] + atomicAdd(&g_cnt[dst], 1);
    g_col[pos] = src;
}

// ---------------- layer1 GEMM: h1 = x @ W1  (tiled 32 nodes/block) --------
__global__ void __launch_bounds__(256) k_gemm1(const float* __restrict__ x,
                                               const float* __restrict__ W1, int N) {
    __shared__ float xs[32][FF];       // 16KB
    __shared__ float ws[FF][HC1];      // 32KB
    int tid = threadIdx.x;
    int nbase = blockIdx.x * 32;
    const float4* W4 = (const float4*)W1;
    float4* ws4 = (float4*)&ws[0][0];
    for (int i = tid; i < FF * HC1 / 4; i += 256) ws4[i] = W4[i];
    for (int i = tid; i < 32 * FF / 4; i += 256) {
        int n = i >> 5;      // 32 float4 per row
        int k4 = i & 31;
        int gn = nbase + n;
        float4 v = (gn < N) ? ((const float4*)x)[(size_t)gn * 32 + k4]
                            : make_float4(0.f, 0.f, 0.f, 0.f);
        ((float4*)&xs[n][0])[k4] = v;
    }
    __syncthreads();
    int cg = tid & 31, ng = tid >> 5;
    int c0 = cg * 2, n0 = ng * 4;
    float acc[4][2] = {};
#pragma unroll
    for (int k = 0; k < FF; k++) {
        float w0 = ws[k][c0], w1 = ws[k][c0 + 1];
#pragma unroll
        for (int i = 0; i < 4; i++) {
            float xv = xs[n0 + i][k];
            acc[i][0] = fmaf(xv, w0, acc[i][0]);
            acc[i][1] = fmaf(xv, w1, acc[i][1]);
        }
    }
#pragma unroll
    for (int i = 0; i < 4; i++) {
        int gn = nbase + n0 + i;
        if (gn < N) {
            g_h1[gn * HC1 + c0]     = acc[i][0];
            g_h1[gn * HC1 + c0 + 1] = acc[i][1];
        }
    }
}

// ---------------- layer1 attention logits: thread per (node,head) ---------
__global__ void k_logits1(const float* __restrict__ att_s,
                          const float* __restrict__ att_d, int N) {
    int i = blockIdx.x * blockDim.x + threadIdx.x;
    if (i >= N * H1) return;
    int n = i >> 3, h = i & 7;
    const float4* hp = (const float4*)&g_h1[n * HC1 + h * C1];
    float4 v0 = hp[0], v1 = hp[1];
    const float4* sp = (const float4*)&att_s[h * C1];
    const float4* dp = (const float4*)&att_d[h * C1];
    float4 s0 = sp[0], s1 = sp[1], d0 = dp[0], d1 = dp[1];
    g_as1[i] = v0.x*s0.x + v0.y*s0.y + v0.z*s0.z + v0.w*s0.w
             + v1.x*s1.x + v1.y*s1.y + v1.z*s1.z + v1.w*s1.w;
    g_ad1[i] = v0.x*d0.x + v0.y*d0.y + v0.z*d0.z + v0.w*d0.w
             + v1.x*d1.x + v1.y*d1.y + v1.z*d1.z + v1.w*d1.w;
}

// ---------------- layer1 aggregate: warp per dst, no atomics --------------
// lane l: head = l>>2, channel pair = (l&3)*2
__global__ void k_agg1(const float* __restrict__ b1, int N) {
    int w = (blockIdx.x * blockDim.x + threadIdx.x) >> 5;
    if (w >= N) return;
    int lane = threadIdx.x & 31;
    int head = lane >> 2, q = lane & 3;
    int r0 = g_rowptr[w], r1 = g_rowptr[w + 1];
    float adv = g_ad1[w * H1 + head];
    // pass 1: exact segment max for this head
    float m = -INFINITY;
    for (int i = r0; i < r1; i++) {
        int src = g_col[i];
        float e = leaky(g_as1[src * H1 + head] + adv);
        m = fmaxf(m, e);
    }
    // pass 2: exp + accumulate
    float s = 0.f, a0 = 0.f, a1 = 0.f;
    for (int i = r0; i < r1; i++) {
        int src = g_col[i];
        float ex = __expf(leaky(g_as1[src * H1 + head] + adv) - m);
        s += ex;
        float2 hv = *(const float2*)&g_h1[src * HC1 + head * C1 + q * 2];
        a0 = fmaf(ex, hv.x, a0);
        a1 = fmaf(ex, hv.y, a1);
    }
    s = (s > 0.f) ? s : 1.f;
    int j = head * C1 + q * 2;
    float v0 = a0 / s + b1[j];
    float v1 = a1 / s + b1[j + 1];
    float2 r;
    r.x = v0 > 0.f ? v0 : expm1f(v0);
    r.y = v1 > 0.f ? v1 : expm1f(v1);
    *(float2*)&g_x2[w * HC1 + j] = r;
}

// ---------------- layer2 GEMM: h2 = x2 @ W2 (tiled 32 nodes/block) --------
__global__ void __launch_bounds__(256) k_gemm2(const float* __restrict__ W2, int N) {
    __shared__ float xs[32][HC1];      // 8KB
    __shared__ float ws[HC1][FF];      // 32KB
    int tid = threadIdx.x;
    int nbase = blockIdx.x * 32;
    const float4* W4 = (const float4*)W2;
    float4* ws4 = (float4*)&ws[0][0];
    for (int i = tid; i < HC1 * FF / 4; i += 256) ws4[i] = W4[i];
    for (int i = tid; i < 32 * HC1 / 4; i += 256) {
        int n = i >> 4;      // 16 float4 per row
        int k4 = i & 15;
        int gn = nbase + n;
        float4 v = (gn < N) ? ((const float4*)g_x2)[(size_t)gn * 16 + k4]
                            : make_float4(0.f, 0.f, 0.f, 0.f);
        ((float4*)&xs[n][0])[k4] = v;
    }
    __syncthreads();
    int cg = tid & 31, ng = tid >> 5;
    int c0 = cg * 4, n0 = ng * 4;
    float acc[4][4] = {};
#pragma unroll
    for (int k = 0; k < HC1; k++) {
        float4 wv = ((const float4*)&ws[k][0])[cg];
#pragma unroll
        for (int i = 0; i < 4; i++) {
            float xv = xs[n0 + i][k];
            acc[i][0] = fmaf(xv, wv.x, acc[i][0]);
            acc[i][1] = fmaf(xv, wv.y, acc[i][1]);
            acc[i][2] = fmaf(xv, wv.z, acc[i][2]);
            acc[i][3] = fmaf(xv, wv.w, acc[i][3]);
        }
    }
#pragma unroll
    for (int i = 0; i < 4; i++) {
        int gn = nbase + n0 + i;
        if (gn < N) {
            float4 r = make_float4(acc[i][0], acc[i][1], acc[i][2], acc[i][3]);
            ((float4*)&g_h2[gn * FF])[cg] = r;
        }
    }
}

// ---------------- layer2 attention logits: warp per node ------------------
__global__ void k_logits2(const float* __restrict__ att_s,
                          const float* __restrict__ att_d, int N) {
    int w = (blockIdx.x * blockDim.x + threadIdx.x) >> 5;
    if (w >= N) return;
    int lane = threadIdx.x & 31;
    float4 v = ((const float4*)&g_h2[w * FF])[lane];
    float4 sa = ((const float4*)att_s)[lane];
    float4 da = ((const float4*)att_d)[lane];
    float s = v.x*sa.x + v.y*sa.y + v.z*sa.z + v.w*sa.w;
    float d = v.x*da.x + v.y*da.y + v.z*da.z + v.w*da.w;
#pragma unroll
    for (int off = 16; off > 0; off >>= 1) {
        s += __shfl_xor_sync(0xFFFFFFFF, s, off);
        d += __shfl_xor_sync(0xFFFFFFFF, d, off);
    }
    if (lane == 0) { g_as2[w] = s; g_ad2[w] = d; }
}

// ---------------- layer2 aggregate: warp per dst, no atomics --------------
__global__ void k_agg2(float* __restrict__ out, const float* __restrict__ b2, int N) {
    int w = (blockIdx.x * blockDim.x + threadIdx.x) >> 5;
    if (w >= N) return;
    int lane = threadIdx.x & 31;
    int r0 = g_rowptr[w], r1 = g_rowptr[w + 1];
    float adv = g_ad2[w];
    float m = -INFINITY;
    for (int i = r0; i < r1; i++) {
        int src = g_col[i];
        float e = leaky(g_as2[src] + adv);
        m = fmaxf(m, e);
    }
    float s = 0.f;
    float4 acc = make_float4(0.f, 0.f, 0.f, 0.f);
    for (int i = r0; i < r1; i++) {
        int src = g_col[i];
        float ex = __expf(leaky(g_as2[src] + adv) - m);
        s += ex;
        float4 hv = ((const float4*)&g_h2[src * FF])[lane];
        acc.x = fmaf(ex, hv.x, acc.x);
        acc.y = fmaf(ex, hv.y, acc.y);
        acc.z = fmaf(ex, hv.z, acc.z);
        acc.w = fmaf(ex, hv.w, acc.w);
    }
    s = (s > 0.f) ? s : 1.f;
    float4 bv = ((const float4*)b2)[lane];
    float4 r;
    r.x = acc.x / s + bv.x;
    r.y = acc.y / s + bv.y;
    r.z = acc.z / s + bv.z;
    r.w = acc.w / s + bv.w;
    ((float4*)&out[w * FF])[lane] = r;
}

// ---------------- launcher ----------------
extern "C" void kernel_launch(void* const* d_in, const int* in_sizes, int n_in,
                              void* d_out, int out_size) {
    const float* x   = (const float*)d_in[0];
    const void*  ei  = d_in[1];
    const float* W1  = (const float*)d_in[2];
    const float* as1 = (const float*)d_in[3];
    const float* ad1 = (const float*)d_in[4];
    const float* b1  = (const float*)d_in[5];
    const float* W2  = (const float*)d_in[6];
    const float* as2 = (const float*)d_in[7];
    const float* ad2 = (const float*)d_in[8];
    const float* b2  = (const float*)d_in[9];
    float*       out = (float*)d_out;

    int N    = in_sizes[0] / FF;     // 50000
    int E    = in_sizes[1] / 2;      // 800000
    int Etot = E + N;

    k_detect<<<1, 1>>>((const int*)ei);

    // CSR build (shared by both layers)
    k_zero_cnt<<<(N + 255) / 256, 256>>>(N);
    k_hist<<<(Etot + 255) / 256, 256>>>(ei, E, Etot);
    k_scan<<<1, 1024>>>(N, Etot);
    k_zero_cnt<<<(N + 255) / 256, 256>>>(N);
    k_scatter<<<(Etot + 255) / 256, 256>>>(ei, E, Etot);

    // layer 1
    k_gemm1<<<(N + 31) / 32, 256>>>(x, W1, N);
    k_logits1<<<(N * H1 + 255) / 256, 256>>>(as1, ad1, N);
    k_agg1<<<(N * 32 + 255) / 256, 256>>>(b1, N);

    // layer 2
    k_gemm2<<<(N + 31) / 32, 256>>>(W2, N);
    k_logits2<<<(N * 32 + 255) / 256, 256>>>(as2, ad2, N);
    k_agg2<<<(N * 32 + 255) / 256, 256>>>(out, b2, N);
}

// round 4
// speedup vs baseline: 2.4808x; 1.2455x over previous
#include <cuda_runtime.h>
#include <cuda_bf16.h>
#include <math.h>

// Fixed problem shape (per reference setup_inputs)
#define NN 50000
#define FF 128
#define H1 8
#define C1 8
#define HC1 64
#define EMAX 900000   // E (800000) + N (50000) self loops

// ---------------- device scratch (no allocation allowed) ----------------
__device__ __align__(16) float g_h1[NN * HC1];   // layer1 features
__device__ __align__(16) float g_x2[NN * HC1];   // ELU(layer1 out)
__device__ __align__(16) float g_h2[NN * FF];    // layer2 features
__device__ float g_as1[NN * H1];
__device__ float g_ad1[NN * H1];
__device__ float g_as2[NN];
__device__ float g_ad2[NN];
__device__ int   g_rowptr[NN + 1];
__device__ int   g_cnt[NN];
__device__ int   g_col[EMAX];                    // src ids grouped by dst
__device__ int   g_bsum[256];                    // block sums for scan
__device__ int   g_is64;

// ---------------- helpers ----------------
__device__ __forceinline__ float leaky(float x) { return x > 0.0f ? x : 0.2f * x; }

__device__ __forceinline__ void load_edge(const void* ei, int E, int e,
                                          int& src, int& dst) {
    if (g_is64) {
        const long long* p = (const long long*)ei;
        src = (int)p[e]; dst = (int)p[E + e];
    } else {
        const int* p = (const int*)ei;
        src = p[e]; dst = p[E + e];
    }
}
__device__ __forceinline__ int load_dst(const void* ei, int E, int e) {
    if (g_is64) return (int)((const long long*)ei)[E + e];
    return ((const int*)ei)[E + e];
}

// ---------------- dtype probe: int64 values <50000 have zero odd words ----
__global__ void k_detect(const int* __restrict__ ei32) {
    int is64 = 1;
#pragma unroll
    for (int i = 0; i < 8; i++)
        if (ei32[2 * i + 1] != 0) is64 = 0;
    g_is64 = is64;
}

// ---------------- CSR build ----------------
__global__ void k_zero_cnt(int N) {
    int i = blockIdx.x * blockDim.x + threadIdx.x;
    if (i < N) g_cnt[i] = 0;
}

__global__ void k_hist(const void* __restrict__ ei, int E, int Etot) {
    int e = blockIdx.x * blockDim.x + threadIdx.x;
    if (e >= Etot) return;
    int dst = (e < E) ? load_dst(ei, E, e) : e - E;
    atomicAdd(&g_cnt[dst], 1);
}

// --- multi-block exclusive scan: A) block sums ---
__global__ void k_bsum(int N) {
    __shared__ int red[256];
    int i = blockIdx.x * 256 + threadIdx.x;
    int c = (i < N) ? g_cnt[i] : 0;
    red[threadIdx.x] = c;
    __syncthreads();
#pragma unroll
    for (int off = 128; off > 0; off >>= 1) {
        if (threadIdx.x < off) red[threadIdx.x] += red[threadIdx.x + off];
        __syncthreads();
    }
    if (threadIdx.x == 0) g_bsum[blockIdx.x] = red[0];
}

// --- B) scan the (<=256) block sums in one block -> exclusive ---
__global__ void k_bscan(int nb) {
    __shared__ int s[256];
    int t = threadIdx.x;
    int v = (t < nb) ? g_bsum[t] : 0;
    s[t] = v;
    __syncthreads();
#pragma unroll
    for (int off = 1; off < 256; off <<= 1) {
        int u = (t >= off) ? s[t - off] : 0;
        __syncthreads();
        s[t] += u;
        __syncthreads();
    }
    if (t < nb) g_bsum[t] = s[t] - v;   // exclusive
}

// --- C) per-block rescan with offset -> g_rowptr ---
__global__ void k_scan2(int N, int Etot) {
    __shared__ int s[256];
    int t = threadIdx.x;
    int i = blockIdx.x * 256 + t;
    int c = (i < N) ? g_cnt[i] : 0;
    s[t] = c;
    __syncthreads();
#pragma unroll
    for (int off = 1; off < 256; off <<= 1) {
        int u = (t >= off) ? s[t - off] : 0;
        __syncthreads();
        s[t] += u;
        __syncthreads();
    }
    if (i < N) {
        int excl = s[t] - c + g_bsum[blockIdx.x];
        g_rowptr[i] = excl;
        if (i == N - 1) g_rowptr[N] = Etot;
    }
}

__global__ void k_scatter(const void* __restrict__ ei, int E, int Etot) {
    int e = blockIdx.x * blockDim.x + threadIdx.x;
    if (e >= Etot) return;
    int src, dst;
    if (e < E) load_edge(ei, E, e, src, dst);
    else       src = dst = e - E;
    int pos = g_rowptr[dst] + atomicAdd(&g_cnt[dst], 1);
    g_col[pos] = src;
}

// ---------------- layer1 GEMM + fused attention logits --------------------
// 32 nodes/block; thread (cg,ng): channels c0=cg*2,+1; nodes n0=ng*4..+3
__global__ void __launch_bounds__(256) k_gemm1(const float* __restrict__ x,
                                               const float* __restrict__ W1,
                                               const float* __restrict__ att_s,
                                               const float* __restrict__ att_d,
                                               int N) {
    __shared__ float xs[32][FF];       // 16KB
    __shared__ float ws[FF][HC1];      // 32KB
    int tid = threadIdx.x;
    int nbase = blockIdx.x * 32;
    const float4* W4 = (const float4*)W1;
    float4* ws4 = (float4*)&ws[0][0];
    for (int i = tid; i < FF * HC1 / 4; i += 256) ws4[i] = W4[i];
    for (int i = tid; i < 32 * FF / 4; i += 256) {
        int n = i >> 5;
        int k4 = i & 31;
        int gn = nbase + n;
        float4 v = (gn < N) ? ((const float4*)x)[(size_t)gn * 32 + k4]
                            : make_float4(0.f, 0.f, 0.f, 0.f);
        ((float4*)&xs[n][0])[k4] = v;
    }
    __syncthreads();
    int cg = tid & 31, ng = tid >> 5;
    int c0 = cg * 2, n0 = ng * 4;
    float acc[4][2] = {};
#pragma unroll
    for (int k = 0; k < FF; k++) {
        float w0 = ws[k][c0], w1 = ws[k][c0 + 1];
#pragma unroll
        for (int i = 0; i < 4; i++) {
            float xv = xs[n0 + i][k];
            acc[i][0] = fmaf(xv, w0, acc[i][0]);
            acc[i][1] = fmaf(xv, w1, acc[i][1]);
        }
    }
    float sa0 = att_s[c0], sa1 = att_s[c0 + 1];
    float da0 = att_d[c0], da1 = att_d[c0 + 1];
    int head = cg >> 2;
#pragma unroll
    for (int i = 0; i < 4; i++) {
        int gn = nbase + n0 + i;
        if (gn < N) {
            g_h1[gn * HC1 + c0]     = acc[i][0];
            g_h1[gn * HC1 + c0 + 1] = acc[i][1];
        }
        // fused logits: reduce over the 4-lane group covering this head
        float s = acc[i][0] * sa0 + acc[i][1] * sa1;
        float d = acc[i][0] * da0 + acc[i][1] * da1;
        s += __shfl_xor_sync(0xFFFFFFFF, s, 1);
        d += __shfl_xor_sync(0xFFFFFFFF, d, 1);
        s += __shfl_xor_sync(0xFFFFFFFF, s, 2);
        d += __shfl_xor_sync(0xFFFFFFFF, d, 2);
        if ((cg & 3) == 0 && gn < N) {
            g_as1[gn * H1 + head] = s;
            g_ad1[gn * H1 + head] = d;
        }
    }
}

// ---------------- layer1 aggregate: warp per dst, no atomics --------------
// lane l: head = l>>2, channel pair = (l&3)*2
__global__ void k_agg1(const float* __restrict__ b1, int N) {
    int w = (blockIdx.x * blockDim.x + threadIdx.x) >> 5;
    if (w >= N) return;
    int lane = threadIdx.x & 31;
    int head = lane >> 2, q = lane & 3;
    int r0 = g_rowptr[w], r1 = g_rowptr[w + 1];
    float adv = g_ad1[w * H1 + head];
    float m = -INFINITY;
    for (int i = r0; i < r1; i++) {
        int src = g_col[i];
        float e = leaky(g_as1[src * H1 + head] + adv);
        m = fmaxf(m, e);
    }
    float s = 0.f, a0 = 0.f, a1 = 0.f;
    for (int i = r0; i < r1; i++) {
        int src = g_col[i];
        float ex = __expf(leaky(g_as1[src * H1 + head] + adv) - m);
        s += ex;
        float2 hv = *(const float2*)&g_h1[src * HC1 + head * C1 + q * 2];
        a0 = fmaf(ex, hv.x, a0);
        a1 = fmaf(ex, hv.y, a1);
    }
    s = (s > 0.f) ? s : 1.f;
    int j = head * C1 + q * 2;
    float v0 = a0 / s + b1[j];
    float v1 = a1 / s + b1[j + 1];
    float2 r;
    r.x = v0 > 0.f ? v0 : expm1f(v0);
    r.y = v1 > 0.f ? v1 : expm1f(v1);
    *(float2*)&g_x2[w * HC1 + j] = r;
}

// ---------------- layer2 GEMM + fused attention logits --------------------
// 32 nodes/block; thread (cg,ng): channels c0=cg*4..+3; nodes n0=ng*4..+3
__global__ void __launch_bounds__(256) k_gemm2(const float* __restrict__ W2,
                                               const float* __restrict__ att_s,
                                               const float* __restrict__ att_d,
                                               int N) {
    __shared__ float xs[32][HC1];      // 8KB
    __shared__ float ws[HC1][FF];      // 32KB
    int tid = threadIdx.x;
    int nbase = blockIdx.x * 32;
    const float4* W4 = (const float4*)W2;
    float4* ws4 = (float4*)&ws[0][0];
    for (int i = tid; i < HC1 * FF / 4; i += 256) ws4[i] = W4[i];
    for (int i = tid; i < 32 * HC1 / 4; i += 256) {
        int n = i >> 4;
        int k4 = i & 15;
        int gn = nbase + n;
        float4 v = (gn < N) ? ((const float4*)g_x2)[(size_t)gn * 16 + k4]
                            : make_float4(0.f, 0.f, 0.f, 0.f);
        ((float4*)&xs[n][0])[k4] = v;
    }
    __syncthreads();
    int cg = tid & 31, ng = tid >> 5;
    int c0 = cg * 4, n0 = ng * 4;
    float acc[4][4] = {};
#pragma unroll
    for (int k = 0; k < HC1; k++) {
        float4 wv = ((const float4*)&ws[k][0])[cg];
#pragma unroll
        for (int i = 0; i < 4; i++) {
            float xv = xs[n0 + i][k];
            acc[i][0] = fmaf(xv, wv.x, acc[i][0]);
            acc[i][1] = fmaf(xv, wv.y, acc[i][1]);
            acc[i][2] = fmaf(xv, wv.z, acc[i][2]);
            acc[i][3] = fmaf(xv, wv.w, acc[i][3]);
        }
    }
    float4 sa = ((const float4*)att_s)[cg];
    float4 da = ((const float4*)att_d)[cg];
#pragma unroll
    for (int i = 0; i < 4; i++) {
        int gn = nbase + n0 + i;
        if (gn < N) {
            float4 r = make_float4(acc[i][0], acc[i][1], acc[i][2], acc[i][3]);
            ((float4*)&g_h2[gn * FF])[cg] = r;
        }
        float s = acc[i][0]*sa.x + acc[i][1]*sa.y + acc[i][2]*sa.z + acc[i][3]*sa.w;
        float d = acc[i][0]*da.x + acc[i][1]*da.y + acc[i][2]*da.z + acc[i][3]*da.w;
#pragma unroll
        for (int off = 16; off > 0; off >>= 1) {
            s += __shfl_xor_sync(0xFFFFFFFF, s, off);
            d += __shfl_xor_sync(0xFFFFFFFF, d, off);
        }
        if (cg == 0 && gn < N) {
            g_as2[gn] = s;
            g_ad2[gn] = d;
        }
    }
}

// ---------------- layer2 aggregate: warp per dst, no atomics --------------
__global__ void k_agg2(float* __restrict__ out, const float* __restrict__ b2, int N) {
    int w = (blockIdx.x * blockDim.x + threadIdx.x) >> 5;
    if (w >= N) return;
    int lane = threadIdx.x & 31;
    int r0 = g_rowptr[w], r1 = g_rowptr[w + 1];
    float adv = g_ad2[w];
    float m = -INFINITY;
    for (int i = r0; i < r1; i++) {
        int src = g_col[i];
        float e = leaky(g_as2[src] + adv);
        m = fmaxf(m, e);
    }
    float s = 0.f;
    float4 acc = make_float4(0.f, 0.f, 0.f, 0.f);
    for (int i = r0; i < r1; i++) {
        int src = g_col[i];
        float ex = __expf(leaky(g_as2[src] + adv) - m);
        s += ex;
        float4 hv = ((const float4*)&g_h2[src * FF])[lane];
        acc.x = fmaf(ex, hv.x, acc.x);
        acc.y = fmaf(ex, hv.y, acc.y);
        acc.z = fmaf(ex, hv.z, acc.z);
        acc.w = fmaf(ex, hv.w, acc.w);
    }
    s = (s > 0.f) ? s : 1.f;
    float4 bv = ((const float4*)b2)[lane];
    float4 r;
    r.x = acc.x / s + bv.x;
    r.y = acc.y / s + bv.y;
    r.z = acc.z / s + bv.z;
    r.w = acc.w / s + bv.w;
    ((float4*)&out[w * FF])[lane] = r;
}

// ---------------- launcher ----------------
extern "C" void kernel_launch(void* const* d_in, const int* in_sizes, int n_in,
                              void* d_out, int out_size) {
    const float* x   = (const float*)d_in[0];
    const void*  ei  = d_in[1];
    const float* W1  = (const float*)d_in[2];
    const float* as1 = (const float*)d_in[3];
    const float* ad1 = (const float*)d_in[4];
    const float* b1  = (const float*)d_in[5];
    const float* W2  = (const float*)d_in[6];
    const float* as2 = (const float*)d_in[7];
    const float* ad2 = (const float*)d_in[8];
    const float* b2  = (const float*)d_in[9];
    float*       out = (float*)d_out;

    int N    = in_sizes[0] / FF;     // 50000
    int E    = in_sizes[1] / 2;      // 800000
    int Etot = E + N;
    int nb   = (N + 255) / 256;      // scan blocks (196)

    k_detect<<<1, 1>>>((const int*)ei);

    // CSR build (shared by both layers)
    k_zero_cnt<<<nb, 256>>>(N);
    k_hist<<<(Etot + 255) / 256, 256>>>(ei, E, Etot);
    k_bsum<<<nb, 256>>>(N);
    k_bscan<<<1, 256>>>(nb);
    k_scan2<<<nb, 256>>>(N, Etot);
    k_zero_cnt<<<nb, 256>>>(N);
    k_scatter<<<(Etot + 255) / 256, 256>>>(ei, E, Etot);

    // layer 1
    k_gemm1<<<(N + 31) / 32, 256>>>(x, W1, as1, ad1, N);
    k_agg1<<<(N * 32 + 255) / 256, 256>>>(b1, N);

    // layer 2
    k_gemm2<<<(N + 31) / 32, 256>>>(W2, as2, ad2, N);
    k_agg2<<<(N * 32 + 255) / 256, 256>>>(out, b2, N);
}

// round 5
// speedup vs baseline: 2.6765x; 1.0789x over previous
#include <cuda_runtime.h>
#include <cuda_bf16.h>
#include <math.h>

// Fixed problem shape (per reference setup_inputs)
#define NN 50000
#define FF 128
#define H1 8
#define C1 8
#define HC1 64
#define EMAX 900000   // E (800000) + N (50000) self loops

// ---------------- device scratch (no allocation allowed) ----------------
__device__ __align__(16) float g_h1[NN * HC1];   // layer1 features
__device__ __align__(16) float g_x2[NN * HC1];   // ELU(layer1 out)
__device__ __align__(16) float g_h2[NN * FF];    // layer2 features
__device__ float g_as1[NN * H1];
__device__ float g_ad1[NN * H1];
__device__ float g_as2[NN];
__device__ float g_ad2[NN];
__device__ int   g_rowptr[NN + 1];
__device__ int   g_cnt[NN];
__device__ int   g_col[EMAX];                    // src ids grouped by dst
__device__ int   g_bsum[256];                    // block sums for scan
__device__ int   g_is64;

// ---------------- helpers ----------------
__device__ __forceinline__ float leaky(float x) { return x > 0.0f ? x : 0.2f * x; }

// packed f32x2 fma (sm_103a FFMA2): d = a*b + c, lanes independent, fp32-exact
__device__ __forceinline__ void fma2(unsigned long long& d, unsigned long long a,
                                     unsigned long long b, unsigned long long c) {
    asm("fma.rn.f32x2 %0, %1, %2, %3;" : "=l"(d) : "l"(a), "l"(b), "l"(c));
}
__device__ __forceinline__ unsigned long long dup2(float x) {
    unsigned long long d;
    unsigned int u = __float_as_uint(x);
    asm("mov.b64 %0, {%1, %2};" : "=l"(d) : "r"(u), "r"(u));
    return d;
}
__device__ __forceinline__ void unpack2(unsigned long long v, float& lo, float& hi) {
    unsigned int a, b;
    asm("mov.b64 {%0, %1}, %2;" : "=r"(a), "=r"(b) : "l"(v));
    lo = __uint_as_float(a);
    hi = __uint_as_float(b);
}

__device__ __forceinline__ void load_edge(const void* ei, int E, int e,
                                          int& src, int& dst) {
    if (g_is64) {
        const long long* p = (const long long*)ei;
        src = (int)p[e]; dst = (int)p[E + e];
    } else {
        const int* p = (const int*)ei;
        src = p[e]; dst = p[E + e];
    }
}
__device__ __forceinline__ int load_dst(const void* ei, int E, int e) {
    if (g_is64) return (int)((const long long*)ei)[E + e];
    return ((const int*)ei)[E + e];
}

// ---------------- zero counts + dtype probe (fused) ----------------------
// int64 values < 50000 have zero odd 32-bit words; int32 array has random ids.
__global__ void k_zero_detect(const int* __restrict__ ei32, int N) {
    int i = blockIdx.x * blockDim.x + threadIdx.x;
    if (i < N) g_cnt[i] = 0;
    if (blockIdx.x == 0 && threadIdx.x == 0) {
        int is64 = 1;
#pragma unroll
        for (int k = 0; k < 8; k++)
            if (ei32[2 * k + 1] != 0) is64 = 0;
        g_is64 = is64;
    }
}

__global__ void k_hist(const void* __restrict__ ei, int E, int Etot) {
    int e = blockIdx.x * blockDim.x + threadIdx.x;
    if (e >= Etot) return;
    int dst = (e < E) ? load_dst(ei, E, e) : e - E;
    atomicAdd(&g_cnt[dst], 1);
}

// --- multi-block exclusive scan: A) block sums ---
__global__ void k_bsum(int N) {
    __shared__ int red[256];
    int i = blockIdx.x * 256 + threadIdx.x;
    red[threadIdx.x] = (i < N) ? g_cnt[i] : 0;
    __syncthreads();
#pragma unroll
    for (int off = 128; off > 0; off >>= 1) {
        if (threadIdx.x < off) red[threadIdx.x] += red[threadIdx.x + off];
        __syncthreads();
    }
    if (threadIdx.x == 0) g_bsum[blockIdx.x] = red[0];
}

// --- B) scan the (<=256) block sums -> exclusive ---
__global__ void k_bscan(int nb) {
    __shared__ int s[256];
    int t = threadIdx.x;
    int v = (t < nb) ? g_bsum[t] : 0;
    s[t] = v;
    __syncthreads();
#pragma unroll
    for (int off = 1; off < 256; off <<= 1) {
        int u = (t >= off) ? s[t - off] : 0;
        __syncthreads();
        s[t] += u;
        __syncthreads();
    }
    if (t < nb) g_bsum[t] = s[t] - v;
}

// --- C) per-block rescan + offset -> g_rowptr; re-zero g_cnt for scatter ---
__global__ void k_scan2(int N, int Etot) {
    __shared__ int s[256];
    int t = threadIdx.x;
    int i = blockIdx.x * 256 + t;
    int c = (i < N) ? g_cnt[i] : 0;
    s[t] = c;
    __syncthreads();
#pragma unroll
    for (int off = 1; off < 256; off <<= 1) {
        int u = (t >= off) ? s[t - off] : 0;
        __syncthreads();
        s[t] += u;
        __syncthreads();
    }
    if (i < N) {
        g_rowptr[i] = s[t] - c + g_bsum[blockIdx.x];
        g_cnt[i] = 0;
        if (i == N - 1) g_rowptr[N] = Etot;
    }
}

__global__ void k_scatter(const void* __restrict__ ei, int E, int Etot) {
    int e = blockIdx.x * blockDim.x + threadIdx.x;
    if (e >= Etot) return;
    int src, dst;
    if (e < E) load_edge(ei, E, e, src, dst);
    else       src = dst = e - E;
    int pos = g_rowptr[dst] + atomicAdd(&g_cnt[dst], 1);
    g_col[pos] = src;
}

// ---------------- layer1 GEMM + fused logits (f32x2 packed FMA) -----------
// 32 nodes/block; cg=tid&15 -> channels c0=cg*4; ng=tid>>4 -> nodes n0=ng*2
__global__ void __launch_bounds__(256) k_gemm1(const float* __restrict__ x,
                                               const float* __restrict__ W1,
                                               const float* __restrict__ att_s,
                                               const float* __restrict__ att_d,
                                               int N) {
    __shared__ float ws[FF * HC1];       // 32KB  [k][c]
    __shared__ float xs[FF * 32];        // 16KB  [k][n] (transposed)
    int tid = threadIdx.x;
    int nbase = blockIdx.x * 32;
    const float4* W4 = (const float4*)W1;
    float4* ws4 = (float4*)ws;
    for (int i = tid; i < FF * HC1 / 4; i += 256) ws4[i] = W4[i];
    for (int i = tid; i < 32 * 32; i += 256) {     // 32 nodes x 32 float4
        int n = i & 31, k4 = i >> 5;
        int gn = nbase + n;
        float4 v = (gn < N) ? ((const float4*)x)[(size_t)gn * 32 + k4]
                            : make_float4(0.f, 0.f, 0.f, 0.f);
        xs[(k4 * 4 + 0) * 32 + n] = v.x;
        xs[(k4 * 4 + 1) * 32 + n] = v.y;
        xs[(k4 * 4 + 2) * 32 + n] = v.z;
        xs[(k4 * 4 + 3) * 32 + n] = v.w;
    }
    __syncthreads();
    int cg = tid & 15, ng = tid >> 4;
    int c0 = cg * 4, n0 = ng * 2;
    unsigned long long acc[2][2] = {};   // [node][chpair]
#pragma unroll
    for (int k = 0; k < FF; k++) {
        ulonglong2 wv = ((const ulonglong2*)(ws + k * HC1))[cg];   // (w0w1)(w2w3)
        float2 xv = ((const float2*)(xs + k * 32))[ng];            // nodes n0,n0+1
        unsigned long long x0 = dup2(xv.x), x1 = dup2(xv.y);
        fma2(acc[0][0], x0, wv.x, acc[0][0]);
        fma2(acc[0][1], x0, wv.y, acc[0][1]);
        fma2(acc[1][0], x1, wv.x, acc[1][0]);
        fma2(acc[1][1], x1, wv.y, acc[1][1]);
    }
    float sa0 = att_s[c0], sa1 = att_s[c0+1], sa2 = att_s[c0+2], sa3 = att_s[c0+3];
    float da0 = att_d[c0], da1 = att_d[c0+1], da2 = att_d[c0+2], da3 = att_d[c0+3];
    int head = cg >> 1;
#pragma unroll
    for (int i = 0; i < 2; i++) {
        float a0, a1, a2, a3;
        unpack2(acc[i][0], a0, a1);
        unpack2(acc[i][1], a2, a3);
        int gn = nbase + n0 + i;
        if (gn < N)
            *((float4*)&g_h1[gn * HC1 + c0]) = make_float4(a0, a1, a2, a3);
        float s = a0*sa0 + a1*sa1 + a2*sa2 + a3*sa3;
        float d = a0*da0 + a1*da1 + a2*da2 + a3*da3;
        s += __shfl_xor_sync(0xFFFFFFFF, s, 1);
        d += __shfl_xor_sync(0xFFFFFFFF, d, 1);
        if ((cg & 1) == 0 && gn < N) {
            g_as1[gn * H1 + head] = s;
            g_ad1[gn * H1 + head] = d;
        }
    }
}

// ---------------- layer1 aggregate: warp per dst, single pass, no max -----
// lane l: head = l>>2, channel pair = (l&3)*2
__global__ void k_agg1(const float* __restrict__ b1, int N) {
    int w = (blockIdx.x * blockDim.x + threadIdx.x) >> 5;
    if (w >= N) return;
    int lane = threadIdx.x & 31;
    int head = lane >> 2, q = lane & 3;
    int r0 = g_rowptr[w], r1 = g_rowptr[w + 1];
    float adv = g_ad1[w * H1 + head];
    float s = 0.f, a0 = 0.f, a1 = 0.f;
    for (int i = r0; i < r1; i++) {
        int src = g_col[i];
        float ex = __expf(leaky(g_as1[src * H1 + head] + adv));
        s += ex;
        float2 hv = *(const float2*)&g_h1[src * HC1 + head * C1 + q * 2];
        a0 = fmaf(ex, hv.x, a0);
        a1 = fmaf(ex, hv.y, a1);
    }
    s = (s > 0.f) ? s : 1.f;
    int j = head * C1 + q * 2;
    float v0 = a0 / s + b1[j];
    float v1 = a1 / s + b1[j + 1];
    float2 r;
    r.x = v0 > 0.f ? v0 : expm1f(v0);
    r.y = v1 > 0.f ? v1 : expm1f(v1);
    *(float2*)&g_x2[w * HC1 + j] = r;
}

// ---------------- layer2 GEMM + fused logits (f32x2 packed FMA) -----------
// 64 nodes/block; cg=tid&31 -> c0=cg*4; ng=tid>>5 -> n0=ng*8 (8 nodes/thread)
__global__ void __launch_bounds__(256) k_gemm2(const float* __restrict__ W2,
                                               const float* __restrict__ att_s,
                                               const float* __restrict__ att_d,
                                               int N) {
    __shared__ float ws[HC1 * FF];       // 32KB [k][c]
    __shared__ float xs[HC1 * 64];       // 16KB [k][n] transposed
    int tid = threadIdx.x;
    int nbase = blockIdx.x * 64;
    const float4* W4 = (const float4*)W2;
    float4* ws4 = (float4*)ws;
    for (int i = tid; i < HC1 * FF / 4; i += 256) ws4[i] = W4[i];
    for (int i = tid; i < 64 * 16; i += 256) {     // 64 nodes x 16 float4
        int n = i & 63, k4 = i >> 6;
        int gn = nbase + n;
        float4 v = (gn < N) ? ((const float4*)g_x2)[(size_t)gn * 16 + k4]
                            : make_float4(0.f, 0.f, 0.f, 0.f);
        xs[(k4 * 4 + 0) * 64 + n] = v.x;
        xs[(k4 * 4 + 1) * 64 + n] = v.y;
        xs[(k4 * 4 + 2) * 64 + n] = v.z;
        xs[(k4 * 4 + 3) * 64 + n] = v.w;
    }
    __syncthreads();
    int cg = tid & 31, ng = tid >> 5;
    int c0 = cg * 4, n0 = ng * 8;
    unsigned long long acc[8][2] = {};   // [node][chpair]
#pragma unroll
    for (int k = 0; k < HC1; k++) {
        ulonglong2 wv = ((const ulonglong2*)(ws + k * FF))[cg];
        float4 xa = ((const float4*)(xs + k * 64))[ng * 2];
        float4 xb = ((const float4*)(xs + k * 64))[ng * 2 + 1];
        unsigned long long xd[8];
        xd[0] = dup2(xa.x); xd[1] = dup2(xa.y); xd[2] = dup2(xa.z); xd[3] = dup2(xa.w);
        xd[4] = dup2(xb.x); xd[5] = dup2(xb.y); xd[6] = dup2(xb.z); xd[7] = dup2(xb.w);
#pragma unroll
        for (int i = 0; i < 8; i++) {
            fma2(acc[i][0], xd[i], wv.x, acc[i][0]);
            fma2(acc[i][1], xd[i], wv.y, acc[i][1]);
        }
    }
    float4 sa = ((const float4*)att_s)[cg];
    float4 da = ((const float4*)att_d)[cg];
#pragma unroll
    for (int i = 0; i < 8; i++) {
        float a0, a1, a2, a3;
        unpack2(acc[i][0], a0, a1);
        unpack2(acc[i][1], a2, a3);
        int gn = nbase + n0 + i;
        if (gn < N)
            *((float4*)&g_h2[gn * FF + c0]) = make_float4(a0, a1, a2, a3);
        float s = a0*sa.x + a1*sa.y + a2*sa.z + a3*sa.w;
        float d = a0*da.x + a1*da.y + a2*da.z + a3*da.w;
#pragma unroll
        for (int off = 16; off > 0; off >>= 1) {
            s += __shfl_xor_sync(0xFFFFFFFF, s, off);
            d += __shfl_xor_sync(0xFFFFFFFF, d, off);
        }
        if (cg == 0 && gn < N) {
            g_as2[gn] = s;
            g_ad2[gn] = d;
        }
    }
}

// ---------------- layer2 aggregate: warp per dst, single pass, no max -----
__global__ void k_agg2(float* __restrict__ out, const float* __restrict__ b2, int N) {
    int w = (blockIdx.x * blockDim.x + threadIdx.x) >> 5;
    if (w >= N) return;
    int lane = threadIdx.x & 31;
    int r0 = g_rowptr[w], r1 = g_rowptr[w + 1];
    float adv = g_ad2[w];
    float s = 0.f;
    float4 acc = make_float4(0.f, 0.f, 0.f, 0.f);
    for (int i = r0; i < r1; i++) {
        int src = g_col[i];
        float ex = __expf(leaky(g_as2[src] + adv));
        s += ex;
        float4 hv = ((const float4*)&g_h2[src * FF])[lane];
        acc.x = fmaf(ex, hv.x, acc.x);
        acc.y = fmaf(ex, hv.y, acc.y);
        acc.z = fmaf(ex, hv.z, acc.z);
        acc.w = fmaf(ex, hv.w, acc.w);
    }
    s = (s > 0.f) ? s : 1.f;
    float4 bv = ((const float4*)b2)[lane];
    float4 r;
    r.x = acc.x / s + bv.x;
    r.y = acc.y / s + bv.y;
    r.z = acc.z / s + bv.z;
    r.w = acc.w / s + bv.w;
    ((float4*)&out[w * FF])[lane] = r;
}

// ---------------- launcher ----------------
extern "C" void kernel_launch(void* const* d_in, const int* in_sizes, int n_in,
                              void* d_out, int out_size) {
    const float* x   = (const float*)d_in[0];
    const void*  ei  = d_in[1];
    const float* W1  = (const float*)d_in[2];
    const float* as1 = (const float*)d_in[3];
    const float* ad1 = (const float*)d_in[4];
    const float* b1  = (const float*)d_in[5];
    const float* W2  = (const float*)d_in[6];
    const float* as2 = (const float*)d_in[7];
    const float* ad2 = (const float*)d_in[8];
    const float* b2  = (const float*)d_in[9];
    float*       out = (float*)d_out;

    int N    = in_sizes[0] / FF;     // 50000
    int E    = in_sizes[1] / 2;      // 800000
    int Etot = E + N;
    int nb   = (N + 255) / 256;      // 196

    // CSR build (shared by both layers)
    k_zero_detect<<<nb, 256>>>((const int*)ei, N);
    k_hist<<<(Etot + 255) / 256, 256>>>(ei, E, Etot);
    k_bsum<<<nb, 256>>>(N);
    k_bscan<<<1, 256>>>(nb);
    k_scan2<<<nb, 256>>>(N, Etot);
    k_scatter<<<(Etot + 255) / 256, 256>>>(ei, E, Etot);

    // layer 1
    k_gemm1<<<(N + 31) / 32, 256>>>(x, W1, as1, ad1, N);
    k_agg1<<<(N * 32 + 255) / 256, 256>>>(b1, N);

    // layer 2
    k_gemm2<<<(N + 63) / 64, 256>>>(W2, as2, ad2, N);
    k_agg2<<<(N * 32 + 255) / 256, 256>>>(out, b2, N);
}

// round 6
// speedup vs baseline: 2.7794x; 1.0385x over previous
#include <cuda_runtime.h>
#include <cuda_fp16.h>
#include <math.h>

// Fixed problem shape (per reference setup_inputs)
#define NN 50000
#define FF 128
#define H1 8
#define C1 8
#define HC1 64
#define EMAX 900000   // E (800000) + N (50000) self loops

// ---------------- device scratch (no allocation allowed) ----------------
__device__ __align__(16) __half g_h1[NN * HC1];  // layer1 features (fp16 storage)
__device__ __align__(16) float  g_x2[NN * HC1];  // ELU(layer1 out) fp32
__device__ __align__(16) __half g_h2[NN * FF];   // layer2 features (fp16 storage)
__device__ float g_as1[NN * H1];
__device__ float g_ad1[NN * H1];
__device__ float g_as2[NN];
__device__ float g_ad2[NN];
__device__ int   g_rowptr[NN + 1];
__device__ int   g_cnt[NN];
__device__ int   g_col[EMAX];                    // src ids grouped by dst
__device__ int   g_bsum[256];                    // block sums for scan
__device__ int   g_is64;

// ---------------- helpers ----------------
__device__ __forceinline__ float leaky(float x) { return x > 0.0f ? x : 0.2f * x; }

// packed f32x2 fma (sm_103a FFMA2)
__device__ __forceinline__ void fma2(unsigned long long& d, unsigned long long a,
                                     unsigned long long b, unsigned long long c) {
    asm("fma.rn.f32x2 %0, %1, %2, %3;" : "=l"(d) : "l"(a), "l"(b), "l"(c));
}
__device__ __forceinline__ unsigned long long dup2(float x) {
    unsigned long long d;
    unsigned int u = __float_as_uint(x);
    asm("mov.b64 %0, {%1, %2};" : "=l"(d) : "r"(u), "r"(u));
    return d;
}
__device__ __forceinline__ void unpack2(unsigned long long v, float& lo, float& hi) {
    unsigned int a, b;
    asm("mov.b64 {%0, %1}, %2;" : "=r"(a), "=r"(b) : "l"(v));
    lo = __uint_as_float(a);
    hi = __uint_as_float(b);
}

__device__ __forceinline__ void load_edge(const void* ei, int E, int e,
                                          int& src, int& dst) {
    if (g_is64) {
        const long long* p = (const long long*)ei;
        src = (int)p[e]; dst = (int)p[E + e];
    } else {
        const int* p = (const int*)ei;
        src = p[e]; dst = p[E + e];
    }
}
__device__ __forceinline__ int load_dst(const void* ei, int E, int e) {
    if (g_is64) return (int)((const long long*)ei)[E + e];
    return ((const int*)ei)[E + e];
}

// ---------------- zero counts + dtype probe (fused) ----------------------
__global__ void k_zero_detect(const int* __restrict__ ei32, int N) {
    int i = blockIdx.x * blockDim.x + threadIdx.x;
    if (i < N) g_cnt[i] = 0;
    if (blockIdx.x == 0 && threadIdx.x == 0) {
        int is64 = 1;
#pragma unroll
        for (int k = 0; k < 8; k++)
            if (ei32[2 * k + 1] != 0) is64 = 0;
        g_is64 = is64;
    }
}

__global__ void k_hist(const void* __restrict__ ei, int E, int Etot) {
    int e = blockIdx.x * blockDim.x + threadIdx.x;
    if (e >= Etot) return;
    int dst = (e < E) ? load_dst(ei, E, e) : e - E;
    atomicAdd(&g_cnt[dst], 1);
}

// --- multi-block exclusive scan: A) block sums ---
__global__ void k_bsum(int N) {
    __shared__ int red[256];
    int i = blockIdx.x * 256 + threadIdx.x;
    red[threadIdx.x] = (i < N) ? g_cnt[i] : 0;
    __syncthreads();
#pragma unroll
    for (int off = 128; off > 0; off >>= 1) {
        if (threadIdx.x < off) red[threadIdx.x] += red[threadIdx.x + off];
        __syncthreads();
    }
    if (threadIdx.x == 0) g_bsum[blockIdx.x] = red[0];
}

// --- B) scan <=256 block sums: shfl warp scan + cross-warp ---
__global__ void k_bscan(int nb) {
    __shared__ int warpsum[8];
    int t = threadIdx.x;
    int lane = t & 31, wid = t >> 5;
    int v = (t < nb) ? g_bsum[t] : 0;
    int sc = v;
#pragma unroll
    for (int off = 1; off < 32; off <<= 1) {
        int u = __shfl_up_sync(0xFFFFFFFF, sc, off);
        if (lane >= off) sc += u;
    }
    if (lane == 31) warpsum[wid] = sc;
    __syncthreads();
    if (wid == 0) {
        int ws = (lane < 8) ? warpsum[lane] : 0;
#pragma unroll
        for (int off = 1; off < 8; off <<= 1) {
            int u = __shfl_up_sync(0xFFFFFFFF, ws, off);
            if (lane >= off) ws += u;
        }
        if (lane < 8) warpsum[lane] = ws;
    }
    __syncthreads();
    int base = (wid > 0) ? warpsum[wid - 1] : 0;
    if (t < nb) g_bsum[t] = base + sc - v;   // exclusive
}

// --- C) per-block rescan + offset -> g_rowptr; re-zero g_cnt -------------
__global__ void k_scan2(int N, int Etot) {
    __shared__ int s[256];
    int t = threadIdx.x;
    int i = blockIdx.x * 256 + t;
    int c = (i < N) ? g_cnt[i] : 0;
    s[t] = c;
    __syncthreads();
#pragma unroll
    for (int off = 1; off < 256; off <<= 1) {
        int u = (t >= off) ? s[t - off] : 0;
        __syncthreads();
        s[t] += u;
        __syncthreads();
    }
    if (i < N) {
        g_rowptr[i] = s[t] - c + g_bsum[blockIdx.x];
        g_cnt[i] = 0;
        if (i == N - 1) g_rowptr[N] = Etot;
    }
}

__global__ void k_scatter(const void* __restrict__ ei, int E, int Etot) {
    int e = blockIdx.x * blockDim.x + threadIdx.x;
    if (e >= Etot) return;
    int src, dst;
    if (e < E) load_edge(ei, E, e, src, dst);
    else       src = dst = e - E;
    int pos = g_rowptr[dst] + atomicAdd(&g_cnt[dst], 1);
    g_col[pos] = src;
}

// ---------------- layer1 GEMM + fused logits (f32x2), fp16 h1 out ---------
// 32 nodes/block; cg=tid&15 -> c0=cg*4; ng=tid>>4 -> nodes n0=ng*2
__global__ void __launch_bounds__(256) k_gemm1(const float* __restrict__ x,
                                               const float* __restrict__ W1,
                                               const float* __restrict__ att_s,
                                               const float* __restrict__ att_d,
                                               int N) {
    __shared__ float ws[FF * HC1];       // 32KB  [k][c]
    __shared__ float xs[FF * 32];        // 16KB  [k][n] transposed
    int tid = threadIdx.x;
    int nbase = blockIdx.x * 32;
    const float4* W4 = (const float4*)W1;
    float4* ws4 = (float4*)ws;
    for (int i = tid; i < FF * HC1 / 4; i += 256) ws4[i] = W4[i];
    for (int i = tid; i < 32 * 32; i += 256) {
        int n = i & 31, k4 = i >> 5;
        int gn = nbase + n;
        float4 v = (gn < N) ? ((const float4*)x)[(size_t)gn * 32 + k4]
                            : make_float4(0.f, 0.f, 0.f, 0.f);
        xs[(k4 * 4 + 0) * 32 + n] = v.x;
        xs[(k4 * 4 + 1) * 32 + n] = v.y;
        xs[(k4 * 4 + 2) * 32 + n] = v.z;
        xs[(k4 * 4 + 3) * 32 + n] = v.w;
    }
    __syncthreads();
    int cg = tid & 15, ng = tid >> 4;
    int c0 = cg * 4, n0 = ng * 2;
    unsigned long long acc[2][2] = {};
#pragma unroll
    for (int k = 0; k < FF; k++) {
        ulonglong2 wv = ((const ulonglong2*)(ws + k * HC1))[cg];
        float2 xv = ((const float2*)(xs + k * 32))[ng];
        unsigned long long x0 = dup2(xv.x), x1 = dup2(xv.y);
        fma2(acc[0][0], x0, wv.x, acc[0][0]);
        fma2(acc[0][1], x0, wv.y, acc[0][1]);
        fma2(acc[1][0], x1, wv.x, acc[1][0]);
        fma2(acc[1][1], x1, wv.y, acc[1][1]);
    }
    float sa0 = att_s[c0], sa1 = att_s[c0+1], sa2 = att_s[c0+2], sa3 = att_s[c0+3];
    float da0 = att_d[c0], da1 = att_d[c0+1], da2 = att_d[c0+2], da3 = att_d[c0+3];
    int head = cg >> 1;
#pragma unroll
    for (int i = 0; i < 2; i++) {
        float a0, a1, a2, a3;
        unpack2(acc[i][0], a0, a1);
        unpack2(acc[i][1], a2, a3);
        int gn = nbase + n0 + i;
        if (gn < N) {
            __half2 p0 = __floats2half2_rn(a0, a1);
            __half2 p1 = __floats2half2_rn(a2, a3);
            *((__half2*)&g_h1[gn * HC1 + c0])     = p0;
            *((__half2*)&g_h1[gn * HC1 + c0 + 2]) = p1;
        }
        float s = a0*sa0 + a1*sa1 + a2*sa2 + a3*sa3;   // fp32 logits (exact)
        float d = a0*da0 + a1*da1 + a2*da2 + a3*da3;
        s += __shfl_xor_sync(0xFFFFFFFF, s, 1);
        d += __shfl_xor_sync(0xFFFFFFFF, d, 1);
        if ((cg & 1) == 0 && gn < N) {
            g_as1[gn * H1 + head] = s;
            g_ad1[gn * H1 + head] = d;
        }
    }
}

// ---------------- layer1 aggregate: warp per dst, single pass -------------
// lane l: head = l>>2, channel pair = (l&3)*2
__global__ void k_agg1(const float* __restrict__ b1, int N) {
    int w = (blockIdx.x * blockDim.x + threadIdx.x) >> 5;
    if (w >= N) return;
    int lane = threadIdx.x & 31;
    int head = lane >> 2, q = lane & 3;
    int r0 = g_rowptr[w], r1 = g_rowptr[w + 1];
    float adv = g_ad1[w * H1 + head];
    float s = 0.f, a0 = 0.f, a1 = 0.f;
    for (int i = r0; i < r1; i++) {
        int src = g_col[i];
        float ex = __expf(leaky(g_as1[src * H1 + head] + adv));
        s += ex;
        __half2 hp = *(const __half2*)&g_h1[src * HC1 + head * C1 + q * 2];
        float2 hv = __half22float2(hp);
        a0 = fmaf(ex, hv.x, a0);
        a1 = fmaf(ex, hv.y, a1);
    }
    s = (s > 0.f) ? s : 1.f;
    int j = head * C1 + q * 2;
    float v0 = a0 / s + b1[j];
    float v1 = a1 / s + b1[j + 1];
    float2 r;
    r.x = v0 > 0.f ? v0 : expm1f(v0);
    r.y = v1 > 0.f ? v1 : expm1f(v1);
    *(float2*)&g_x2[w * HC1 + j] = r;
}

// ---------------- layer2 GEMM + fused logits (f32x2), fp16 h2 out ---------
// 64 nodes/block; cg=tid&31 -> c0=cg*4; ng=tid>>5 -> n0=ng*8
__global__ void __launch_bounds__(256) k_gemm2(const float* __restrict__ W2,
                                               const float* __restrict__ att_s,
                                               const float* __restrict__ att_d,
                                               int N) {
    __shared__ float ws[HC1 * FF];       // 32KB [k][c]
    __shared__ float xs[HC1 * 64];       // 16KB [k][n] transposed
    int tid = threadIdx.x;
    int nbase = blockIdx.x * 64;
    const float4* W4 = (const float4*)W2;
    float4* ws4 = (float4*)ws;
    for (int i = tid; i < HC1 * FF / 4; i += 256) ws4[i] = W4[i];
    for (int i = tid; i < 64 * 16; i += 256) {
        int n = i & 63, k4 = i >> 6;
        int gn = nbase + n;
        float4 v = (gn < N) ? ((const float4*)g_x2)[(size_t)gn * 16 + k4]
                            : make_float4(0.f, 0.f, 0.f, 0.f);
        xs[(k4 * 4 + 0) * 64 + n] = v.x;
        xs[(k4 * 4 + 1) * 64 + n] = v.y;
        xs[(k4 * 4 + 2) * 64 + n] = v.z;
        xs[(k4 * 4 + 3) * 64 + n] = v.w;
    }
    __syncthreads();
    int cg = tid & 31, ng = tid >> 5;
    int c0 = cg * 4, n0 = ng * 8;
    unsigned long long acc[8][2] = {};
#pragma unroll
    for (int k = 0; k < HC1; k++) {
        ulonglong2 wv = ((const ulonglong2*)(ws + k * FF))[cg];
        float4 xa = ((const float4*)(xs + k * 64))[ng * 2];
        float4 xb = ((const float4*)(xs + k * 64))[ng * 2 + 1];
        unsigned long long xd[8];
        xd[0] = dup2(xa.x); xd[1] = dup2(xa.y); xd[2] = dup2(xa.z); xd[3] = dup2(xa.w);
        xd[4] = dup2(xb.x); xd[5] = dup2(xb.y); xd[6] = dup2(xb.z); xd[7] = dup2(xb.w);
#pragma unroll
        for (int i = 0; i < 8; i++) {
            fma2(acc[i][0], xd[i], wv.x, acc[i][0]);
            fma2(acc[i][1], xd[i], wv.y, acc[i][1]);
        }
    }
    float4 sa = ((const float4*)att_s)[cg];
    float4 da = ((const float4*)att_d)[cg];
#pragma unroll
    for (int i = 0; i < 8; i++) {
        float a0, a1, a2, a3;
        unpack2(acc[i][0], a0, a1);
        unpack2(acc[i][1], a2, a3);
        int gn = nbase + n0 + i;
        if (gn < N) {
            __half2 p0 = __floats2half2_rn(a0, a1);
            __half2 p1 = __floats2half2_rn(a2, a3);
            *((__half2*)&g_h2[gn * FF + c0])     = p0;
            *((__half2*)&g_h2[gn * FF + c0 + 2]) = p1;
        }
        float s = a0*sa.x + a1*sa.y + a2*sa.z + a3*sa.w;  // fp32 logits (exact)
        float d = a0*da.x + a1*da.y + a2*da.z + a3*da.w;
#pragma unroll
        for (int off = 16; off > 0; off >>= 1) {
            s += __shfl_xor_sync(0xFFFFFFFF, s, off);
            d += __shfl_xor_sync(0xFFFFFFFF, d, off);
        }
        if (cg == 0 && gn < N) {
            g_as2[gn] = s;
            g_ad2[gn] = d;
        }
    }
}

// ---------------- layer2 aggregate: warp per dst, single pass -------------
// lane handles 4 channels: fp16 gather (8B/lane), fp32 accumulate
__global__ void k_agg2(float* __restrict__ out, const float* __restrict__ b2, int N) {
    int w = (blockIdx.x * blockDim.x + threadIdx.x) >> 5;
    if (w >= N) return;
    int lane = threadIdx.x & 31;
    int r0 = g_rowptr[w], r1 = g_rowptr[w + 1];
    float adv = g_ad2[w];
    float s = 0.f;
    float4 acc = make_float4(0.f, 0.f, 0.f, 0.f);
    for (int i = r0; i < r1; i++) {
        int src = g_col[i];
        float ex = __expf(leaky(g_as2[src] + adv));
        s += ex;
        uint2 raw = ((const uint2*)&g_h2[src * FF])[lane];
        float2 h01 = __half22float2(*(const __half2*)&raw.x);
        float2 h23 = __half22float2(*(const __half2*)&raw.y);
        acc.x = fmaf(ex, h01.x, acc.x);
        acc.y = fmaf(ex, h01.y, acc.y);
        acc.z = fmaf(ex, h23.x, acc.z);
        acc.w = fmaf(ex, h23.y, acc.w);
    }
    s = (s > 0.f) ? s : 1.f;
    float4 bv = ((const float4*)b2)[lane];
    float4 r;
    r.x = acc.x / s + bv.x;
    r.y = acc.y / s + bv.y;
    r.z = acc.z / s + bv.z;
    r.w = acc.w / s + bv.w;
    ((float4*)&out[w * FF])[lane] = r;
}

// ---------------- launcher ----------------
extern "C" void kernel_launch(void* const* d_in, const int* in_sizes, int n_in,
                              void* d_out, int out_size) {
    const float* x   = (const float*)d_in[0];
    const void*  ei  = d_in[1];
    const float* W1  = (const float*)d_in[2];
    const float* as1 = (const float*)d_in[3];
    const float* ad1 = (const float*)d_in[4];
    const float* b1  = (const float*)d_in[5];
    const float* W2  = (const float*)d_in[6];
    const float* as2 = (const float*)d_in[7];
    const float* ad2 = (const float*)d_in[8];
    const float* b2  = (const float*)d_in[9];
    float*       out = (float*)d_out;

    int N    = in_sizes[0] / FF;     // 50000
    int E    = in_sizes[1] / 2;      // 800000
    int Etot = E + N;
    int nb   = (N + 255) / 256;      // 196

    // CSR build (shared by both layers)
    k_zero_detect<<<nb, 256>>>((const int*)ei, N);
    k_hist<<<(Etot + 255) / 256, 256>>>(ei, E, Etot);
    k_bsum<<<nb, 256>>>(N);
    k_bscan<<<1, 256>>>(nb);
    k_scan2<<<nb, 256>>>(N, Etot);
    k_scatter<<<(Etot + 255) / 256, 256>>>(ei, E, Etot);

    // layer 1
    k_gemm1<<<(N + 31) / 32, 256>>>(x, W1, as1, ad1, N);
    k_agg1<<<(N * 32 + 255) / 256, 256>>>(b1, N);

    // layer 2
    k_gemm2<<<(N + 63) / 64, 256>>>(W2, as2, ad2, N);
    k_agg2<<<(N * 32 + 255) / 256, 256>>>(out, b2, N);
}

// round 7
// speedup vs baseline: 2.8141x; 1.0125x over previous
#include <cuda_runtime.h>
#include <cuda_fp16.h>
#include <math.h>

// Fixed problem shape (per reference setup_inputs)
#define NN 50000
#define FF 128
#define H1 8
#define C1 8
#define HC1 64
#define EMAX 900000   // E (800000) + N (50000) self loops

// ---------------- device scratch (no allocation allowed) ----------------
__device__ __align__(16) __half g_h1[NN * HC1];  // layer1 features (fp16)
__device__ __align__(16) float  g_x2[NN * HC1];  // ELU(layer1 out) fp32
__device__ __align__(16) __half g_h2[NN * FF];   // layer2 features (fp16)
__device__ float g_as1[NN * H1];
__device__ float g_ad1[NN * H1];
__device__ float g_as2[NN];
__device__ float g_ad2[NN];
__device__ int   g_rowptr[NN + 1];
__device__ int   g_cnt[NN];
__device__ int   g_col[EMAX];                    // src ids grouped by dst
__device__ int   g_bsum[256];                    // raw block sums for scan
__device__ int   g_is64;

// ---------------- helpers ----------------
__device__ __forceinline__ float leaky(float x) { return x > 0.0f ? x : 0.2f * x; }

__device__ __forceinline__ void fma2(unsigned long long& d, unsigned long long a,
                                     unsigned long long b, unsigned long long c) {
    asm("fma.rn.f32x2 %0, %1, %2, %3;" : "=l"(d) : "l"(a), "l"(b), "l"(c));
}
__device__ __forceinline__ unsigned long long dup2(float x) {
    unsigned long long d;
    unsigned int u = __float_as_uint(x);
    asm("mov.b64 %0, {%1, %2};" : "=l"(d) : "r"(u), "r"(u));
    return d;
}
__device__ __forceinline__ void unpack2(unsigned long long v, float& lo, float& hi) {
    unsigned int a, b;
    asm("mov.b64 {%0, %1}, %2;" : "=r"(a), "=r"(b) : "l"(v));
    lo = __uint_as_float(a);
    hi = __uint_as_float(b);
}

__device__ __forceinline__ void load_edge(const void* ei, int E, int e,
                                          int& src, int& dst) {
    if (g_is64) {
        const long long* p = (const long long*)ei;
        src = (int)p[e]; dst = (int)p[E + e];
    } else {
        const int* p = (const int*)ei;
        src = p[e]; dst = p[E + e];
    }
}
__device__ __forceinline__ int load_dst(const void* ei, int E, int e) {
    if (g_is64) return (int)((const long long*)ei)[E + e];
    return ((const int*)ei)[E + e];
}

// ---------------- zero counts + dtype probe (fused) ----------------------
__global__ void k_zero_detect(const int* __restrict__ ei32, int N) {
    int i = blockIdx.x * blockDim.x + threadIdx.x;
    if (i < N) g_cnt[i] = 0;
    if (blockIdx.x == 0 && threadIdx.x == 0) {
        int is64 = 1;
#pragma unroll
        for (int k = 0; k < 8; k++)
            if (ei32[2 * k + 1] != 0) is64 = 0;
        g_is64 = is64;
    }
}

__global__ void k_hist(const void* __restrict__ ei, int E, int Etot) {
    int e = blockIdx.x * blockDim.x + threadIdx.x;
    if (e >= Etot) return;
    int dst = (e < E) ? load_dst(ei, E, e) : e - E;
    atomicAdd(&g_cnt[dst], 1);
}

// --- A) per-block sums of counts ---
__global__ void k_bsum(int N) {
    __shared__ int red[256];
    int i = blockIdx.x * 256 + threadIdx.x;
    red[threadIdx.x] = (i < N) ? g_cnt[i] : 0;
    __syncthreads();
#pragma unroll
    for (int off = 128; off > 0; off >>= 1) {
        if (threadIdx.x < off) red[threadIdx.x] += red[threadIdx.x + off];
        __syncthreads();
    }
    if (threadIdx.x == 0) g_bsum[blockIdx.x] = red[0];
}

// --- B) per-block local scan; each block reduces its own bsum prefix ------
// (nb <= 256 guaranteed: N=50000 -> 196 blocks)
__global__ void k_scan2(int N, int Etot) {
    __shared__ int s[256];
    __shared__ int wred[8];
    int t = threadIdx.x;
    int lane = t & 31, wid = t >> 5;

    // block offset = sum of g_bsum[j] for j < blockIdx.x
    int bv = (t < blockIdx.x) ? g_bsum[t] : 0;
#pragma unroll
    for (int off = 16; off > 0; off >>= 1)
        bv += __shfl_xor_sync(0xFFFFFFFF, bv, off);
    if (lane == 0) wred[wid] = bv;

    // local exclusive scan of counts
    int i = blockIdx.x * 256 + t;
    int c = (i < N) ? g_cnt[i] : 0;
    s[t] = c;
    __syncthreads();
#pragma unroll
    for (int off = 1; off < 256; off <<= 1) {
        int u = (t >= off) ? s[t - off] : 0;
        __syncthreads();
        s[t] += u;
        __syncthreads();
    }
    int boff = wred[0] + wred[1] + wred[2] + wred[3]
             + wred[4] + wred[5] + wred[6] + wred[7];
    if (i < N) {
        g_rowptr[i] = s[t] - c + boff;
        g_cnt[i] = 0;
        if (i == N - 1) g_rowptr[N] = Etot;
    }
}

__global__ void k_scatter(const void* __restrict__ ei, int E, int Etot) {
    int e = blockIdx.x * blockDim.x + threadIdx.x;
    if (e >= Etot) return;
    int src, dst;
    if (e < E) load_edge(ei, E, e, src, dst);
    else       src = dst = e - E;
    int pos = g_rowptr[dst] + atomicAdd(&g_cnt[dst], 1);
    g_col[pos] = src;
}

// ---------------- layer1 GEMM + fused logits (f32x2), fp16 h1 out ---------
__global__ void __launch_bounds__(256) k_gemm1(const float* __restrict__ x,
                                               const float* __restrict__ W1,
                                               const float* __restrict__ att_s,
                                               const float* __restrict__ att_d,
                                               int N) {
    __shared__ float ws[FF * HC1];       // 32KB [k][c]
    __shared__ float xs[FF * 32];        // 16KB [k][n] transposed
    int tid = threadIdx.x;
    int nbase = blockIdx.x * 32;
    const float4* W4 = (const float4*)W1;
    float4* ws4 = (float4*)ws;
    for (int i = tid; i < FF * HC1 / 4; i += 256) ws4[i] = W4[i];
    for (int i = tid; i < 32 * 32; i += 256) {
        int n = i & 31, k4 = i >> 5;
        int gn = nbase + n;
        float4 v = (gn < N) ? ((const float4*)x)[(size_t)gn * 32 + k4]
                            : make_float4(0.f, 0.f, 0.f, 0.f);
        xs[(k4 * 4 + 0) * 32 + n] = v.x;
        xs[(k4 * 4 + 1) * 32 + n] = v.y;
        xs[(k4 * 4 + 2) * 32 + n] = v.z;
        xs[(k4 * 4 + 3) * 32 + n] = v.w;
    }
    __syncthreads();
    int cg = tid & 15, ng = tid >> 4;
    int c0 = cg * 4, n0 = ng * 2;
    unsigned long long acc[2][2] = {};
#pragma unroll
    for (int k = 0; k < FF; k++) {
        ulonglong2 wv = ((const ulonglong2*)(ws + k * HC1))[cg];
        float2 xv = ((const float2*)(xs + k * 32))[ng];
        unsigned long long x0 = dup2(xv.x), x1 = dup2(xv.y);
        fma2(acc[0][0], x0, wv.x, acc[0][0]);
        fma2(acc[0][1], x0, wv.y, acc[0][1]);
        fma2(acc[1][0], x1, wv.x, acc[1][0]);
        fma2(acc[1][1], x1, wv.y, acc[1][1]);
    }
    float sa0 = att_s[c0], sa1 = att_s[c0+1], sa2 = att_s[c0+2], sa3 = att_s[c0+3];
    float da0 = att_d[c0], da1 = att_d[c0+1], da2 = att_d[c0+2], da3 = att_d[c0+3];
    int head = cg >> 1;
#pragma unroll
    for (int i = 0; i < 2; i++) {
        float a0, a1, a2, a3;
        unpack2(acc[i][0], a0, a1);
        unpack2(acc[i][1], a2, a3);
        int gn = nbase + n0 + i;
        if (gn < N) {
            *((__half2*)&g_h1[gn * HC1 + c0])     = __floats2half2_rn(a0, a1);
            *((__half2*)&g_h1[gn * HC1 + c0 + 2]) = __floats2half2_rn(a2, a3);
        }
        float s = a0*sa0 + a1*sa1 + a2*sa2 + a3*sa3;
        float d = a0*da0 + a1*da1 + a2*da2 + a3*da3;
        s += __shfl_xor_sync(0xFFFFFFFF, s, 1);
        d += __shfl_xor_sync(0xFFFFFFFF, d, 1);
        if ((cg & 1) == 0 && gn < N) {
            g_as1[gn * H1 + head] = s;
            g_ad1[gn * H1 + head] = d;
        }
    }
}

// ---------------- layer1 aggregate: warp/dst, 4x pipelined ----------------
// lane l: head = l>>2, channel pair = (l&3)*2
__global__ void k_agg1(const float* __restrict__ b1, int N) {
    int w = (blockIdx.x * blockDim.x + threadIdx.x) >> 5;
    if (w >= N) return;
    int lane = threadIdx.x & 31;
    int head = lane >> 2, q = lane & 3;
    int r0 = g_rowptr[w], r1 = g_rowptr[w + 1];
    float adv = g_ad1[w * H1 + head];
    float s = 0.f, a0 = 0.f, a1 = 0.f;
    int i = r0;
    for (; i + 4 <= r1; i += 4) {
        int s0 = g_col[i], s1 = g_col[i+1], s2 = g_col[i+2], s3 = g_col[i+3];
        float l0 = g_as1[s0 * H1 + head];
        float l1 = g_as1[s1 * H1 + head];
        float l2 = g_as1[s2 * H1 + head];
        float l3 = g_as1[s3 * H1 + head];
        __half2 p0 = *(const __half2*)&g_h1[s0 * HC1 + head * C1 + q * 2];
        __half2 p1 = *(const __half2*)&g_h1[s1 * HC1 + head * C1 + q * 2];
        __half2 p2 = *(const __half2*)&g_h1[s2 * HC1 + head * C1 + q * 2];
        __half2 p3 = *(const __half2*)&g_h1[s3 * HC1 + head * C1 + q * 2];
        float e0 = __expf(leaky(l0 + adv));
        float e1 = __expf(leaky(l1 + adv));
        float e2 = __expf(leaky(l2 + adv));
        float e3 = __expf(leaky(l3 + adv));
        s += (e0 + e1) + (e2 + e3);
        float2 h0 = __half22float2(p0), h1v = __half22float2(p1);
        float2 h2v = __half22float2(p2), h3 = __half22float2(p3);
        a0 = fmaf(e0, h0.x, a0);  a1 = fmaf(e0, h0.y, a1);
        a0 = fmaf(e1, h1v.x, a0); a1 = fmaf(e1, h1v.y, a1);
        a0 = fmaf(e2, h2v.x, a0); a1 = fmaf(e2, h2v.y, a1);
        a0 = fmaf(e3, h3.x, a0);  a1 = fmaf(e3, h3.y, a1);
    }
    for (; i < r1; i++) {
        int src = g_col[i];
        float ex = __expf(leaky(g_as1[src * H1 + head] + adv));
        s += ex;
        float2 hv = __half22float2(*(const __half2*)&g_h1[src * HC1 + head * C1 + q * 2]);
        a0 = fmaf(ex, hv.x, a0);
        a1 = fmaf(ex, hv.y, a1);
    }
    s = (s > 0.f) ? s : 1.f;
    int j = head * C1 + q * 2;
    float v0 = a0 / s + b1[j];
    float v1 = a1 / s + b1[j + 1];
    float2 r;
    r.x = v0 > 0.f ? v0 : expm1f(v0);
    r.y = v1 > 0.f ? v1 : expm1f(v1);
    *(float2*)&g_x2[w * HC1 + j] = r;
}

// ---------------- layer2 GEMM + fused logits (f32x2), fp16 h2 out ---------
__global__ void __launch_bounds__(256) k_gemm2(const float* __restrict__ W2,
                                               const float* __restrict__ att_s,
                                               const float* __restrict__ att_d,
                                               int N) {
    __shared__ float ws[HC1 * FF];       // 32KB [k][c]
    __shared__ float xs[HC1 * 64];       // 16KB [k][n] transposed
    int tid = threadIdx.x;
    int nbase = blockIdx.x * 64;
    const float4* W4 = (const float4*)W2;
    float4* ws4 = (float4*)ws;
    for (int i = tid; i < HC1 * FF / 4; i += 256) ws4[i] = W4[i];
    for (int i = tid; i < 64 * 16; i += 256) {
        int n = i & 63, k4 = i >> 6;
        int gn = nbase + n;
        float4 v = (gn < N) ? ((const float4*)g_x2)[(size_t)gn * 16 + k4]
                            : make_float4(0.f, 0.f, 0.f, 0.f);
        xs[(k4 * 4 + 0) * 64 + n] = v.x;
        xs[(k4 * 4 + 1) * 64 + n] = v.y;
        xs[(k4 * 4 + 2) * 64 + n] = v.z;
        xs[(k4 * 4 + 3) * 64 + n] = v.w;
    }
    __syncthreads();
    int cg = tid & 31, ng = tid >> 5;
    int c0 = cg * 4, n0 = ng * 8;
    unsigned long long acc[8][2] = {};
#pragma unroll
    for (int k = 0; k < HC1; k++) {
        ulonglong2 wv = ((const ulonglong2*)(ws + k * FF))[cg];
        float4 xa = ((const float4*)(xs + k * 64))[ng * 2];
        float4 xb = ((const float4*)(xs + k * 64))[ng * 2 + 1];
        unsigned long long xd[8];
        xd[0] = dup2(xa.x); xd[1] = dup2(xa.y); xd[2] = dup2(xa.z); xd[3] = dup2(xa.w);
        xd[4] = dup2(xb.x); xd[5] = dup2(xb.y); xd[6] = dup2(xb.z); xd[7] = dup2(xb.w);
#pragma unroll
        for (int i = 0; i < 8; i++) {
            fma2(acc[i][0], xd[i], wv.x, acc[i][0]);
            fma2(acc[i][1], xd[i], wv.y, acc[i][1]);
        }
    }
    float4 sa = ((const float4*)att_s)[cg];
    float4 da = ((const float4*)att_d)[cg];
#pragma unroll
    for (int i = 0; i < 8; i++) {
        float a0, a1, a2, a3;
        unpack2(acc[i][0], a0, a1);
        unpack2(acc[i][1], a2, a3);
        int gn = nbase + n0 + i;
        if (gn < N) {
            *((__half2*)&g_h2[gn * FF + c0])     = __floats2half2_rn(a0, a1);
            *((__half2*)&g_h2[gn * FF + c0 + 2]) = __floats2half2_rn(a2, a3);
        }
        float s = a0*sa.x + a1*sa.y + a2*sa.z + a3*sa.w;
        float d = a0*da.x + a1*da.y + a2*da.z + a3*da.w;
#pragma unroll
        for (int off = 16; off > 0; off >>= 1) {
            s += __shfl_xor_sync(0xFFFFFFFF, s, off);
            d += __shfl_xor_sync(0xFFFFFFFF, d, off);
        }
        if (cg == 0 && gn < N) {
            g_as2[gn] = s;
            g_ad2[gn] = d;
        }
    }
}

// ---------------- layer2 aggregate: warp/dst, 4x pipelined ----------------
__global__ void k_agg2(float* __restrict__ out, const float* __restrict__ b2, int N) {
    int w = (blockIdx.x * blockDim.x + threadIdx.x) >> 5;
    if (w >= N) return;
    int lane = threadIdx.x & 31;
    int r0 = g_rowptr[w], r1 = g_rowptr[w + 1];
    float adv = g_ad2[w];
    float s = 0.f;
    float4 acc = make_float4(0.f, 0.f, 0.f, 0.f);
    int i = r0;
    for (; i + 4 <= r1; i += 4) {
        int s0 = g_col[i], s1 = g_col[i+1], s2 = g_col[i+2], s3 = g_col[i+3];
        float l0 = g_as2[s0], l1 = g_as2[s1], l2 = g_as2[s2], l3 = g_as2[s3];
        uint2 w0 = ((const uint2*)&g_h2[s0 * FF])[lane];
        uint2 w1 = ((const uint2*)&g_h2[s1 * FF])[lane];
        uint2 w2 = ((const uint2*)&g_h2[s2 * FF])[lane];
        uint2 w3 = ((const uint2*)&g_h2[s3 * FF])[lane];
        float e0 = __expf(leaky(l0 + adv));
        float e1 = __expf(leaky(l1 + adv));
        float e2 = __expf(leaky(l2 + adv));
        float e3 = __expf(leaky(l3 + adv));
        s += (e0 + e1) + (e2 + e3);
        float2 a01, a23;
        a01 = __half22float2(*(const __half2*)&w0.x);
        a23 = __half22float2(*(const __half2*)&w0.y);
        acc.x = fmaf(e0, a01.x, acc.x); acc.y = fmaf(e0, a01.y, acc.y);
        acc.z = fmaf(e0, a23.x, acc.z); acc.w = fmaf(e0, a23.y, acc.w);
        a01 = __half22float2(*(const __half2*)&w1.x);
        a23 = __half22float2(*(const __half2*)&w1.y);
        acc.x = fmaf(e1, a01.x, acc.x); acc.y = fmaf(e1, a01.y, acc.y);
        acc.z = fmaf(e1, a23.x, acc.z); acc.w = fmaf(e1, a23.y, acc.w);
        a01 = __half22float2(*(const __half2*)&w2.x);
        a23 = __half22float2(*(const __half2*)&w2.y);
        acc.x = fmaf(e2, a01.x, acc.x); acc.y = fmaf(e2, a01.y, acc.y);
        acc.z = fmaf(e2, a23.x, acc.z); acc.w = fmaf(e2, a23.y, acc.w);
        a01 = __half22float2(*(const __half2*)&w3.x);
        a23 = __half22float2(*(const __half2*)&w3.y);
        acc.x = fmaf(e3, a01.x, acc.x); acc.y = fmaf(e3, a01.y, acc.y);
        acc.z = fmaf(e3, a23.x, acc.z); acc.w = fmaf(e3, a23.y, acc.w);
    }
    for (; i < r1; i++) {
        int src = g_col[i];
        float ex = __expf(leaky(g_as2[src] + adv));
        s += ex;
        uint2 raw = ((const uint2*)&g_h2[src * FF])[lane];
        float2 h01 = __half22float2(*(const __half2*)&raw.x);
        float2 h23 = __half22float2(*(const __half2*)&raw.y);
        acc.x = fmaf(ex, h01.x, acc.x);
        acc.y = fmaf(ex, h01.y, acc.y);
        acc.z = fmaf(ex, h23.x, acc.z);
        acc.w = fmaf(ex, h23.y, acc.w);
    }
    s = (s > 0.f) ? s : 1.f;
    float4 bv = ((const float4*)b2)[lane];
    float4 r;
    r.x = acc.x / s + bv.x;
    r.y = acc.y / s + bv.y;
    r.z = acc.z / s + bv.z;
    r.w = acc.w / s + bv.w;
    ((float4*)&out[w * FF])[lane] = r;
}

// ---------------- launcher ----------------
extern "C" void kernel_launch(void* const* d_in, const int* in_sizes, int n_in,
                              void* d_out, int out_size) {
    const float* x   = (const float*)d_in[0];
    const void*  ei  = d_in[1];
    const float* W1  = (const float*)d_in[2];
    const float* as1 = (const float*)d_in[3];
    const float* ad1 = (const float*)d_in[4];
    const float* b1  = (const float*)d_in[5];
    const float* W2  = (const float*)d_in[6];
    const float* as2 = (const float*)d_in[7];
    const float* ad2 = (const float*)d_in[8];
    const float* b2  = (const float*)d_in[9];
    float*       out = (float*)d_out;

    int N    = in_sizes[0] / FF;     // 50000
    int E    = in_sizes[1] / 2;      // 800000
    int Etot = E + N;
    int nb   = (N + 255) / 256;      // 196 (<=256 required by k_scan2)

    // CSR build (shared by both layers)
    k_zero_detect<<<nb, 256>>>((const int*)ei, N);
    k_hist<<<(Etot + 255) / 256, 256>>>(ei, E, Etot);
    k_bsum<<<nb, 256>>>(N);
    k_scan2<<<nb, 256>>>(N, Etot);
    k_scatter<<<(Etot + 255) / 256, 256>>>(ei, E, Etot);

    // layer 1
    k_gemm1<<<(N + 31) / 32, 256>>>(x, W1, as1, ad1, N);
    k_agg1<<<(N * 32 + 255) / 256, 256>>>(b1, N);

    // layer 2
    k_gemm2<<<(N + 63) / 64, 256>>>(W2, as2, ad2, N);
    k_agg2<<<(N * 32 + 255) / 256, 256>>>(out, b2, N);
}